// round 5
// baseline (speedup 1.0000x reference)
#include <cuda_runtime.h>
#include <cuda_bf16.h>

// CustomEmbedding: out[t, :] = sin((id/1000)*(i+1)) if id<1000 else weight[id, :]
// Tokens: 8*4096 = 32768, DIM = 512 floats = 128 float4 per row.
// One WARP per token: 32 threads, each moves FOUR float4s (j, j+32, j+64, j+96)
// -> per-thread MLP=4, fully coalesced 512B segments, warp-uniform branch.
// 256-thread block = 8 tokens; grid = 4096 blocks.
// Output stores are streaming (evict-first) so the ~48 MiB weight working
// set stays L2-resident for repeat-id gathers.

#define DIM4 128            // 512 floats / 4
#define THR_PER_TOK 32      // one warp per token; each thread: 4 float4
#define TOK_PER_BLK 8
#define BLK_THREADS (THR_PER_TOK * TOK_PER_BLK)   // 256

__global__ void __launch_bounds__(BLK_THREADS)
embed_kernel(const int* __restrict__ x,
             const float4* __restrict__ w,   // [VOCAB, DIM4]
             float4* __restrict__ out,       // [N, DIM4]
             int n_tokens)
{
    int local_t = threadIdx.x >> 5;                   // warp id in block, 0..7
    int j       = threadIdx.x & 31;                   // lane -> float4 idx 0..31
    int t       = blockIdx.x * TOK_PER_BLK + local_t;
    if (t >= n_tokens) return;

    int id = __ldg(x + t);

    float4 v0, v1, v2, v3;
    if (id < 1000) {
        // numeric token: sin((id/1000) * (i+1)), i = element index
        float s = (float)id * 1e-3f;
        #define SIN4(dst, jj)                          \
            { float b = (float)((jj) * 4);             \
              dst.x = sinf(s * (b + 1.0f));            \
              dst.y = sinf(s * (b + 2.0f));            \
              dst.z = sinf(s * (b + 3.0f));            \
              dst.w = sinf(s * (b + 4.0f)); }
        SIN4(v0, j)
        SIN4(v1, j + 32)
        SIN4(v2, j + 64)
        SIN4(v3, j + 96)
        #undef SIN4
    } else {
        const float4* row = w + (size_t)id * DIM4;
        // 4 independent loads, front-batched -> MLP=4
        v0 = __ldg(row + j);
        v1 = __ldg(row + j + 32);
        v2 = __ldg(row + j + 64);
        v3 = __ldg(row + j + 96);
    }

    float4* orow = out + (size_t)t * DIM4;
    __stcs(orow + j,      v0);
    __stcs(orow + j + 32, v1);
    __stcs(orow + j + 64, v2);
    __stcs(orow + j + 96, v3);
}

extern "C" void kernel_launch(void* const* d_in, const int* in_sizes, int n_in,
                              void* d_out, int out_size)
{
    // metadata order: x (int32), weight (float32), num_value (int32), is_num (bool)
    const int*    x = (const int*)d_in[0];
    const float4* w = (const float4*)d_in[1];
    float4*     out = (float4*)d_out;

    int n_tokens = in_sizes[0];           // 32768
    int blocks   = (n_tokens + TOK_PER_BLK - 1) / TOK_PER_BLK;

    embed_kernel<<<blocks, BLK_THREADS>>>(x, w, out, n_tokens);
}

// round 6
// speedup vs baseline: 1.0417x; 1.0417x over previous
#include <cuda_runtime.h>
#include <cuda_bf16.h>

// CustomEmbedding: out[t, :] = sin((id/1000)*(i+1)) if id<1000 else weight[id, :]
// Tokens: 8*4096 = 32768, DIM = 512 floats = 128 float4 per row.
// One WARP per TWO tokens:
//   - both ids fetched with a single int2 LDG (broadcast)
//   - 8 independent row LDG.128s front-batched (per-thread MLP = 8)
//   - 8 streaming STG.128s (evict-first keeps weight table L2-resident)
// 256-thread block = 8 warps = 16 tokens; grid = 2048 blocks.

#define DIM4 128            // 512 floats / 4

__device__ __forceinline__ float4 sin4(float s, int jj) {
    float b = (float)(jj * 4);
    float4 v;
    v.x = sinf(s * (b + 1.0f));
    v.y = sinf(s * (b + 2.0f));
    v.z = sinf(s * (b + 3.0f));
    v.w = sinf(s * (b + 4.0f));
    return v;
}

__global__ void __launch_bounds__(256)
embed_kernel(const int2* __restrict__ x2,    // token ids, viewed as pairs
             const float4* __restrict__ w,   // [VOCAB, DIM4]
             float4* __restrict__ out,       // [N, DIM4]
             int n_pairs)
{
    int warp = (blockIdx.x * blockDim.x + threadIdx.x) >> 5;  // global warp = pair idx
    int j    = threadIdx.x & 31;                              // lane -> float4 idx base
    if (warp >= n_pairs) return;

    int2 ids = __ldg(x2 + warp);        // one 8B load, broadcast across warp
    int  id0 = ids.x, id1 = ids.y;
    int  t0  = warp * 2;

    const float4* r0 = w + (size_t)id0 * DIM4;
    const float4* r1 = w + (size_t)id1 * DIM4;

    float4 a0, a1, a2, a3, b0, b1, b2, b3;

    if (id0 >= 1000 && id1 >= 1000) {
        // fast path (~96% of warps): 8 independent loads, front-batched
        a0 = __ldg(r0 + j);
        a1 = __ldg(r0 + j + 32);
        a2 = __ldg(r0 + j + 64);
        a3 = __ldg(r0 + j + 96);
        b0 = __ldg(r1 + j);
        b1 = __ldg(r1 + j + 32);
        b2 = __ldg(r1 + j + 64);
        b3 = __ldg(r1 + j + 96);
    } else {
        if (id0 < 1000) {
            float s = (float)id0 * 1e-3f;
            a0 = sin4(s, j); a1 = sin4(s, j + 32);
            a2 = sin4(s, j + 64); a3 = sin4(s, j + 96);
        } else {
            a0 = __ldg(r0 + j);      a1 = __ldg(r0 + j + 32);
            a2 = __ldg(r0 + j + 64); a3 = __ldg(r0 + j + 96);
        }
        if (id1 < 1000) {
            float s = (float)id1 * 1e-3f;
            b0 = sin4(s, j); b1 = sin4(s, j + 32);
            b2 = sin4(s, j + 64); b3 = sin4(s, j + 96);
        } else {
            b0 = __ldg(r1 + j);      b1 = __ldg(r1 + j + 32);
            b2 = __ldg(r1 + j + 64); b3 = __ldg(r1 + j + 96);
        }
    }

    float4* o0 = out + (size_t)t0 * DIM4;
    float4* o1 = o0 + DIM4;
    __stcs(o0 + j,      a0);
    __stcs(o0 + j + 32, a1);
    __stcs(o0 + j + 64, a2);
    __stcs(o0 + j + 96, a3);
    __stcs(o1 + j,      b0);
    __stcs(o1 + j + 32, b1);
    __stcs(o1 + j + 64, b2);
    __stcs(o1 + j + 96, b3);
}

extern "C" void kernel_launch(void* const* d_in, const int* in_sizes, int n_in,
                              void* d_out, int out_size)
{
    // metadata order: x (int32), weight (float32), num_value (int32), is_num (bool)
    const int2*   x2 = (const int2*)d_in[0];
    const float4* w  = (const float4*)d_in[1];
    float4*      out = (float4*)d_out;

    int n_tokens = in_sizes[0];           // 32768 (even)
    int n_pairs  = n_tokens / 2;          // 16384 warps
    int blocks   = (n_pairs * 32 + 255) / 256;   // 2048

    embed_kernel<<<blocks, 256>>>(x2, w, out, n_pairs);
}